// round 15
// baseline (speedup 1.0000x reference)
#include <cuda_runtime.h>
#include <cuda_bf16.h>
#include <math.h>
#include <stdint.h>

#define N_NODES 4096
#define IN_F    512
#define OUT_F   64
#define HEADS   8
#define NEG_BIG (-9000000000000000.0f)

// ---------------- scratch (allocation-free contract) ----------------
__device__ float    g_T [HEADS * OUT_F];                     // column sums of Wh
__device__ float    g_M [(size_t)N_NODES * HEADS * OUT_F];   // 8 MB partial sums
// Wh in mma.sync B-fragment layout:
// entry (head, kc(0..255), g(0..7), lane(0..31)) = {hi0, hi1, lo0, lo1}
//   hi0 = pack(Wh[m0][o], Wh[m0+1][o]) hi parts, m0 = 16*kc + 2*(lane&3),
//   hi1 = same at m0+8; lo0/lo1 = residuals; o = 8*g + (lane>>2)
__device__ uint4    g_Bf[(size_t)HEADS * 256 * 8 * 32];      // 8 MB
__device__ uint32_t g_adjbits[(size_t)N_NODES * (N_NODES / 32)]; // 2 MB

// ---------------- helpers ----------------
__device__ __forceinline__ uint32_t smem_to_u32(const void* p) {
    uint32_t a;
    asm("{ .reg .u64 t; cvta.to.shared.u64 t, %1; cvt.u32.u64 %0, t; }" : "=r"(a) : "l"(p));
    return a;
}
__device__ __forceinline__ void ldm4(uint32_t* r, uint32_t addr) {
    asm volatile("ldmatrix.sync.aligned.m8n8.x4.shared.b16 {%0,%1,%2,%3}, [%4];"
        : "=r"(r[0]), "=r"(r[1]), "=r"(r[2]), "=r"(r[3]) : "r"(addr));
}
__device__ __forceinline__ void mma16816(float* c, const uint32_t* a, const uint32_t* b) {
    asm volatile("mma.sync.aligned.m16n8k16.row.col.f32.bf16.bf16.f32 "
        "{%0,%1,%2,%3}, {%4,%5,%6,%7}, {%8,%9}, {%0,%1,%2,%3};"
        : "+f"(c[0]), "+f"(c[1]), "+f"(c[2]), "+f"(c[3])
        : "r"(a[0]), "r"(a[1]), "r"(a[2]), "r"(a[3]), "r"(b[0]), "r"(b[1]));
}
__device__ __forceinline__ uint32_t pack_bf16x2(float lo, float hi) {
    uint32_t d;
    asm("cvt.rn.bf16x2.f32 %0, %1, %2;" : "=r"(d) : "f"(hi), "f"(lo));
    return d;
}
// 2 low bits of x -> packed bf16x2 of {0.0, 1.0}
__device__ __forceinline__ uint32_t expand2(uint32_t x) {
    return ((x & 1u) | ((x << 15) & 0x10000u)) * 0x3F80u;
}
// split (x, y) into packed hi-bf16x2 and lo-bf16x2 (x in low half)
__device__ __forceinline__ void split_pack(float x, float y, uint32_t& hi, uint32_t& lo) {
    __nv_bfloat16 hx = __float2bfloat16(x);
    __nv_bfloat16 hy = __float2bfloat16(y);
    hi = (uint32_t)__bfloat16_as_ushort(hx) | ((uint32_t)__bfloat16_as_ushort(hy) << 16);
    lo = pack_bf16x2(x - __bfloat162float(hx), y - __bfloat162float(hy));
}

// ---------------------------------------------------------------------------
// Kernel ADJBITS (separate, smem-free, high occupancy): pack adj to bitmask.
// ---------------------------------------------------------------------------
__global__ __launch_bounds__(256) void adjbits_kernel(const int* __restrict__ adj)
{
    const size_t idx = (size_t)blockIdx.x * 256 + threadIdx.x;
    const int* p = adj + idx * 32;
    uint32_t w = 0;
    #pragma unroll
    for (int q = 0; q < 8; q++) {
        int4 v = *(const int4*)(p + q * 4);
        w |= (v.x > 0 ? 1u : 0u) << (q * 4 + 0);
        w |= (v.y > 0 ? 1u : 0u) << (q * 4 + 1);
        w |= (v.z > 0 ? 1u : 0u) << (q * 4 + 2);
        w |= (v.w > 0 ? 1u : 0u) << (q * 4 + 3);
    }
    g_adjbits[idx] = w;
}

// ---------------------------------------------------------------------------
// Kernel PREP (wh only): Wh = h@W via bf16 hi/lo HMMA
// (acc = h_hi*W_hi + h_hi*W_lo + h_lo*W_hi), writes T + fragment-layout g_Bf.
// Grid (256): x = n-tile(32) | head<<5. 256 threads, 8 warps x (16n x 64o).
// ---------------------------------------------------------------------------
#define P_AHI  0
#define P_ALO  12288
#define P_BHI  24576
#define P_BLO  30720
#define P_TRED 36864
#define PREP_SMEM 38912

__global__ __launch_bounds__(256) void prep_kernel(const float* __restrict__ h,
                                                   const float* __restrict__ W)
{
    __shared__ __align__(16) char sm[PREP_SMEM];
    const int t = threadIdx.x;

    const uint32_t smem_u = smem_to_u32(sm);
    const int n0   = (blockIdx.x & 31) * 128;
    const int head = blockIdx.x >> 5;
    const int lane = t & 31;
    const int w16  = (t >> 5) * 16;              // warp's n-row base

    const float* Wb = W + head * IN_F * OUT_F;

    // staging roles
    const int ar  = t >> 1;                      // A row 0..127
    const int aq  = t & 1;                       // A k-half (8 floats each)
    const int bk  = t >> 4;                      // B k 0..15
    const int bo4 = (t & 15) << 2;               // B o base

    // ldmatrix offsets
    const uint32_t aLd = (uint32_t)(w16 + (lane & 15)) * 48 + (uint32_t)(lane >> 4) * 16;
    const uint32_t bLd = (uint32_t)((lane & 7) + ((lane >> 4) & 1) * 8) * 48
                       + (uint32_t)((lane >> 3) & 1) * 16;

    float acc[8][4] = {};

    #define WH_STAGE(C, BUF) do {                                                \
        const int _k0 = (C) * 16;                                                \
        /* A: h rows, hi/lo split */                                             \
        {                                                                        \
            const float* _p = h + (size_t)(n0 + ar) * IN_F + _k0 + aq * 8;       \
            float4 v0 = *(const float4*)_p;                                      \
            float4 v1 = *(const float4*)(_p + 4);                                \
            uint32_t hu[4], lu[4];                                               \
            split_pack(v0.x, v0.y, hu[0], lu[0]);                                \
            split_pack(v0.z, v0.w, hu[1], lu[1]);                                \
            split_pack(v1.x, v1.y, hu[2], lu[2]);                                \
            split_pack(v1.z, v1.w, hu[3], lu[3]);                                \
            const uint32_t _off = (uint32_t)(BUF) * 6144 + ar * 48 + aq * 16;    \
            *(uint4*)(sm + P_AHI + _off) = *(uint4*)hu;                          \
            *(uint4*)(sm + P_ALO + _off) = *(uint4*)lu;                          \
        }                                                                        \
        /* B: W^T tile [o][k], hi/lo split, u16 scatter */                       \
        {                                                                        \
            float4 wv = *(const float4*)(Wb + (size_t)(_k0 + bk) * OUT_F + bo4); \
            const float _w[4] = {wv.x, wv.y, wv.z, wv.w};                        \
            uint16_t* _bh = (uint16_t*)(sm + P_BHI + (BUF) * 3072);              \
            uint16_t* _bl = (uint16_t*)(sm + P_BLO + (BUF) * 3072);              \
            _Pragma("unroll")                                                    \
            for (int _j = 0; _j < 4; _j++) {                                     \
                __nv_bfloat16 _hi = __float2bfloat16(_w[_j]);                    \
                __nv_bfloat16 _lo = __float2bfloat16(_w[_j] - __bfloat162float(_hi)); \
                const int _i = (bo4 + _j) * 24 + bk;                             \
                _bh[_i] = __bfloat16_as_ushort(_hi);                             \
                _bl[_i] = __bfloat16_as_ushort(_lo);                             \
            }                                                                    \
        }                                                                        \
    } while (0)

    WH_STAGE(0, 0);
    __syncthreads();

    for (int c = 0; c < 32; c++) {
        const int buf = c & 1;
        if (c + 1 < 32) WH_STAGE(c + 1, 1 - buf);

        uint32_t ahi[4], alo[4];
        ldm4(ahi, smem_u + P_AHI + buf * 6144 + aLd);
        ldm4(alo, smem_u + P_ALO + buf * 6144 + aLd);
        #pragma unroll
        for (int g = 0; g < 4; g++) {
            uint32_t bh[4], bl[4];
            ldm4(bh, smem_u + P_BHI + buf * 3072 + bLd + g * 768);
            ldm4(bl, smem_u + P_BLO + buf * 3072 + bLd + g * 768);
            mma16816(acc[2 * g + 0], ahi, bh + 0);
            mma16816(acc[2 * g + 1], ahi, bh + 2);
            mma16816(acc[2 * g + 0], ahi, bl + 0);
            mma16816(acc[2 * g + 1], ahi, bl + 2);
            mma16816(acc[2 * g + 0], alo, bh + 0);
            mma16816(acc[2 * g + 1], alo, bh + 2);
        }
        __syncthreads();
    }

    // ---- T partials: shuffle-reduce over rows, stash per-warp ----
    {
        float* tr = (float*)(sm + P_TRED) + (t >> 5) * 64;
        #pragma unroll
        for (int f = 0; f < 8; f++) {
            float t0 = acc[f][0] + acc[f][2];
            float t1 = acc[f][1] + acc[f][3];
            #pragma unroll
            for (int off = 4; off < 32; off <<= 1) {
                t0 += __shfl_xor_sync(0xffffffffu, t0, off);
                t1 += __shfl_xor_sync(0xffffffffu, t1, off);
            }
            if (lane < 4) {
                tr[8 * f + 2 * lane]     = t0;
                tr[8 * f + 2 * lane + 1] = t1;
            }
        }
    }

    // ---- f32 staging of full 128x64 Wh tile ----
    {
        float* sfp = (float*)sm;   // [128][64]
        const int mr = w16 + (lane >> 2);
        #pragma unroll
        for (int f = 0; f < 8; f++) {
            const int o = 8 * f + 2 * (lane & 3);
            sfp[mr * 64 + o]           = acc[f][0];
            sfp[mr * 64 + o + 1]       = acc[f][1];
            sfp[(mr + 8) * 64 + o]     = acc[f][2];
            sfp[(mr + 8) * 64 + o + 1] = acc[f][3];
        }
    }
    __syncthreads();

    // ---- T atomics ----
    if (t < 64) {
        const float* tr = (const float*)(sm + P_TRED);
        float s = 0.f;
        #pragma unroll
        for (int q = 0; q < 8; q++) s += tr[q * 64 + t];
        atomicAdd(&g_T[head * OUT_F + t], s);
    }

    // ---- gather into B-fragment layout, write g_Bf ----
    {
        const float* sfp = (const float*)sm;
        const int kcl  = t >> 5;                 // local k-chunk 0..7
        const int ln   = t & 31;
        const int m0   = kcl * 16 + 2 * (ln & 3);
        const int orow = ln >> 2;
        uint4* dst = g_Bf + ((size_t)(head * 256 + (n0 >> 4) + kcl)) * 256 + ln;
        #pragma unroll
        for (int g = 0; g < 8; g++) {
            const int o = 8 * g + orow;
            float x0 = sfp[m0 * 64 + o];
            float x1 = sfp[(m0 + 1) * 64 + o];
            float x8 = sfp[(m0 + 8) * 64 + o];
            float x9 = sfp[(m0 + 9) * 64 + o];
            uint32_t h0, l0, h1, l1;
            split_pack(x0, x1, h0, l0);
            split_pack(x8, x9, h1, l1);
            dst[g * 32] = make_uint4(h0, h1, l0, l1);
        }
    }
}

// ---------------------------------------------------------------------------
// Kernel B v5: smem-free, barrier-free masked aggregation.
// Grid (64, 8): x = n-tile(32) | khalf<<5; y = head. 128 threads, 4 warps.
// Warp: 32n x 64o x 2048m partial of M = adj @ (Whhi+Whlo); A from bitmask in
// regs, B fragments via direct LDG.128 from g_Bf. atomicAdd into g_M.
// ---------------------------------------------------------------------------
__global__ __launch_bounds__(128, 4) void attn_mma5_kernel()
{
    const int tid  = threadIdx.x;
    const int wid  = tid >> 5;
    const int lane = tid & 31;
    const int n0   = (blockIdx.x & 31) * 128;
    const int kh   = blockIdx.x >> 5;
    const int head = blockIdx.y;

    const int nb = n0 + wid * 32;
    const int r  = lane >> 2;
    const uint32_t* bp0 = g_adjbits + (size_t)(nb + r +  0) * 128 + kh * 64;
    const uint32_t* bp1 = g_adjbits + (size_t)(nb + r +  8) * 128 + kh * 64;
    const uint32_t* bp2 = g_adjbits + (size_t)(nb + r + 16) * 128 + kh * 64;
    const uint32_t* bp3 = g_adjbits + (size_t)(nb + r + 24) * 128 + kh * 64;

    const uint4* bfp = g_Bf + ((size_t)(head * 256 + kh * 128)) * 256 + lane;
    const int shb = (lane & 3) * 2;

    float cM[2][8][4] = {};

    for (int c4 = 0; c4 < 16; c4++) {
        const uint4 bw0 = *(const uint4*)(bp0 + c4 * 4);
        const uint4 bw1 = *(const uint4*)(bp1 + c4 * 4);
        const uint4 bw2 = *(const uint4*)(bp2 + c4 * 4);
        const uint4 bw3 = *(const uint4*)(bp3 + c4 * 4);
        #pragma unroll
        for (int cc = 0; cc < 4; cc++) {
            const uint32_t w0 = cc == 0 ? bw0.x : cc == 1 ? bw0.y : cc == 2 ? bw0.z : bw0.w;
            const uint32_t w1 = cc == 0 ? bw1.x : cc == 1 ? bw1.y : cc == 2 ? bw1.z : bw1.w;
            const uint32_t w2 = cc == 0 ? bw2.x : cc == 1 ? bw2.y : cc == 2 ? bw2.z : bw2.w;
            const uint32_t w3 = cc == 0 ? bw3.x : cc == 1 ? bw3.y : cc == 2 ? bw3.z : bw3.w;
            #pragma unroll
            for (int half = 0; half < 2; half++) {
                const int sh = half * 16 + shb;
                uint32_t a0[4], a1[4];
                a0[0] = expand2(w0 >> sh);       a0[1] = expand2(w1 >> sh);
                a0[2] = expand2(w0 >> (sh + 8)); a0[3] = expand2(w1 >> (sh + 8));
                a1[0] = expand2(w2 >> sh);       a1[1] = expand2(w3 >> sh);
                a1[2] = expand2(w2 >> (sh + 8)); a1[3] = expand2(w3 >> (sh + 8));
                const uint4* bp = bfp + (size_t)((c4 * 8 + cc * 2 + half) << 8);
                #pragma unroll
                for (int g = 0; g < 8; g++) {
                    const uint4 f = bp[g * 32];
                    uint32_t bh[2] = {f.x, f.y};
                    uint32_t bl[2] = {f.z, f.w};
                    mma16816(cM[0][g], a0, bh);
                    mma16816(cM[1][g], a1, bh);
                    mma16816(cM[0][g], a0, bl);
                    mma16816(cM[1][g], a1, bl);
                }
            }
        }
    }

    // ---- epilogue: atomicAdd partial M ----
    const int col0 = (lane & 3) * 2;
    const int rowA = nb + (lane >> 2);
    #pragma unroll
    for (int tt = 0; tt < 2; tt++) {
        float* p0 = g_M + (size_t)(rowA + tt * 16) * (HEADS * OUT_F) + head * OUT_F;
        float* p1 = p0 + 8 * (HEADS * OUT_F);
        #pragma unroll
        for (int g2 = 0; g2 < 8; g2++) {
            const int o = g2 * 8 + col0;
            atomicAdd(p0 + o,     cM[tt][g2][0]);
            atomicAdd(p0 + o + 1, cM[tt][g2][1]);
            atomicAdd(p1 + o,     cM[tt][g2][2]);
            atomicAdd(p1 + o + 1, cM[tt][g2][3]);
        }
    }
}

// ---------------------------------------------------------------------------
// Fixup: out = elu( NEG_BIG * (T[col] - M) ), vectorized float4.
// ---------------------------------------------------------------------------
__global__ __launch_bounds__(256) void fixup_kernel(float* __restrict__ out)
{
    const int idx  = blockIdx.x * 256 + threadIdx.x;
    const int col  = (idx << 2) & 511;
    float4 m = *(const float4*)(g_M + (size_t)idx * 4);
    float4 tv = *(const float4*)(g_T + col);
    float x0 = NEG_BIG * (tv.x - m.x);
    float x1 = NEG_BIG * (tv.y - m.y);
    float x2 = NEG_BIG * (tv.z - m.z);
    float x3 = NEG_BIG * (tv.w - m.w);
    x0 = x0 > 0.f ? x0 : (expf(x0) - 1.0f);
    x1 = x1 > 0.f ? x1 : (expf(x1) - 1.0f);
    x2 = x2 > 0.f ? x2 : (expf(x2) - 1.0f);
    x3 = x3 > 0.f ? x3 : (expf(x3) - 1.0f);
    *(float4*)(out + (size_t)idx * 4) = make_float4(x0, x1, x2, x3);
}

// ---------------------------------------------------------------------------
extern "C" void kernel_launch(void* const* d_in, const int* in_sizes, int n_in,
                              void* d_out, int out_size)
{
    const float* h   = (const float*)d_in[0];   // [4096, 512] f32
    const int*   adj = (const int*)  d_in[1];   // [4096, 4096] i32
    const float* W   = (const float*)d_in[2];   // [8, 512, 64] f32
    float*       out = (float*)d_out;           // [4096, 512] f32

    (void)in_sizes; (void)n_in; (void)out_size;

    static float* tptr = nullptr;
    static float* mptr = nullptr;
    if (!tptr) cudaGetSymbolAddress((void**)&tptr, g_T);
    if (!mptr) cudaGetSymbolAddress((void**)&mptr, g_M);

    cudaMemsetAsync(tptr, 0, HEADS * OUT_F * sizeof(float), 0);
    cudaMemsetAsync(mptr, 0, (size_t)N_NODES * HEADS * OUT_F * sizeof(float), 0);

    adjbits_kernel<<<(N_NODES * (N_NODES / 32)) / 256, 256>>>(adj);

    prep_kernel<<<256, 256>>>(h, W);

    dim3 gB(64, HEADS);
    attn_mma5_kernel<<<gB, 128>>>();

    fixup_kernel<<<(N_NODES * HEADS * OUT_F / 4) / 256, 256>>>(out);
}

// round 16
// speedup vs baseline: 1.0271x; 1.0271x over previous
#include <cuda_runtime.h>
#include <cuda_bf16.h>
#include <math.h>
#include <stdint.h>

#define N_NODES 4096
#define IN_F    512
#define OUT_F   64
#define HEADS   8
#define NEG_BIG (-9000000000000000.0f)

// ---------------- scratch (allocation-free contract) ----------------
__device__ float         g_T  [HEADS * OUT_F];                    // column sums of Wh
__device__ float         g_M  [(size_t)N_NODES * HEADS * OUT_F];  // 8 MB partial sums
// B operands, tiled: element (head, m, o) at (head*512 + m/8)*512 + o*8 + m%8
__device__ __nv_bfloat16 g_Bhi[(size_t)HEADS * 512 * 64 * 8];     // 4 MB
__device__ __nv_bfloat16 g_Blo[(size_t)HEADS * 512 * 64 * 8];     // 4 MB
__device__ uint32_t      g_adjbits[(size_t)N_NODES * (N_NODES / 32)]; // 2 MB

// ---------------- helpers ----------------
__device__ __forceinline__ uint32_t smem_to_u32(const void* p) {
    uint32_t a;
    asm("{ .reg .u64 t; cvta.to.shared.u64 t, %1; cvt.u32.u64 %0, t; }" : "=r"(a) : "l"(p));
    return a;
}
__device__ __forceinline__ void ldm4(uint32_t* r, uint32_t addr) {
    asm volatile("ldmatrix.sync.aligned.m8n8.x4.shared.b16 {%0,%1,%2,%3}, [%4];"
        : "=r"(r[0]), "=r"(r[1]), "=r"(r[2]), "=r"(r[3]) : "r"(addr));
}
__device__ __forceinline__ void mma16816(float* c, const uint32_t* a, const uint32_t* b) {
    asm volatile("mma.sync.aligned.m16n8k16.row.col.f32.bf16.bf16.f32 "
        "{%0,%1,%2,%3}, {%4,%5,%6,%7}, {%8,%9}, {%0,%1,%2,%3};"
        : "+f"(c[0]), "+f"(c[1]), "+f"(c[2]), "+f"(c[3])
        : "r"(a[0]), "r"(a[1]), "r"(a[2]), "r"(a[3]), "r"(b[0]), "r"(b[1]));
}
__device__ __forceinline__ uint32_t pack_bf16x2(float lo, float hi) {
    uint32_t d;
    asm("cvt.rn.bf16x2.f32 %0, %1, %2;" : "=r"(d) : "f"(hi), "f"(lo));
    return d;
}
// 2 low bits of x -> packed bf16x2 of {0.0, 1.0}
__device__ __forceinline__ uint32_t expand2(uint32_t x) {
    return ((x & 1u) | ((x << 15) & 0x10000u)) * 0x3F80u;
}
// split (x, y) into packed hi-bf16x2 and lo-bf16x2 (x in low half)
__device__ __forceinline__ void split_pack(float x, float y, uint32_t& hi, uint32_t& lo) {
    __nv_bfloat16 hx = __float2bfloat16(x);
    __nv_bfloat16 hy = __float2bfloat16(y);
    hi = (uint32_t)__bfloat16_as_ushort(hx) | ((uint32_t)__bfloat16_as_ushort(hy) << 16);
    lo = pack_bf16x2(x - __bfloat162float(hx), y - __bfloat162float(hy));
}

// ---------------------------------------------------------------------------
// Kernel ADJBITS (separate, smem-free, high occupancy): pack adj to bitmask.
// ---------------------------------------------------------------------------
__global__ __launch_bounds__(256) void adjbits_kernel(const int* __restrict__ adj)
{
    const size_t idx = (size_t)blockIdx.x * 256 + threadIdx.x;
    const int* p = adj + idx * 32;
    uint32_t w = 0;
    #pragma unroll
    for (int q = 0; q < 8; q++) {
        int4 v = *(const int4*)(p + q * 4);
        w |= (v.x > 0 ? 1u : 0u) << (q * 4 + 0);
        w |= (v.y > 0 ? 1u : 0u) << (q * 4 + 1);
        w |= (v.z > 0 ? 1u : 0u) << (q * 4 + 2);
        w |= (v.w > 0 ? 1u : 0u) << (q * 4 + 3);
    }
    g_adjbits[idx] = w;
}

// ---------------------------------------------------------------------------
// Kernel PREP (wh only, R12-proven): Wh = h@W via bf16 hi/lo HMMA
// (acc = h_hi*W_hi + h_hi*W_lo + h_lo*W_hi), writes T + tiled g_Bhi/g_Blo.
// Grid (256): x = n-tile(32) | head<<5. 256 threads, 8 warps x (16n x 64o).
// ---------------------------------------------------------------------------
#define P_AHI  0
#define P_ALO  12288
#define P_BHI  24576
#define P_BLO  30720
#define P_TRED 36864
#define PREP_SMEM 38912

__global__ __launch_bounds__(256) void prep_kernel(const float* __restrict__ h,
                                                   const float* __restrict__ W)
{
    __shared__ __align__(16) char sm[PREP_SMEM];
    const int t = threadIdx.x;

    const uint32_t smem_u = smem_to_u32(sm);
    const int n0   = (blockIdx.x & 31) * 128;
    const int head = blockIdx.x >> 5;
    const int lane = t & 31;
    const int w16  = (t >> 5) * 16;              // warp's n-row base

    const float* Wb = W + head * IN_F * OUT_F;

    // staging roles
    const int ar  = t >> 1;                      // A row 0..127
    const int aq  = t & 1;                       // A k-half (8 floats each)
    const int bk  = t >> 4;                      // B k 0..15
    const int bo4 = (t & 15) << 2;               // B o base

    // ldmatrix offsets
    const uint32_t aLd = (uint32_t)(w16 + (lane & 15)) * 48 + (uint32_t)(lane >> 4) * 16;
    const uint32_t bLd = (uint32_t)((lane & 7) + ((lane >> 4) & 1) * 8) * 48
                       + (uint32_t)((lane >> 3) & 1) * 16;

    float acc[8][4] = {};

    #define WH_STAGE(C, BUF) do {                                                \
        const int _k0 = (C) * 16;                                                \
        /* A: h rows, hi/lo split */                                             \
        {                                                                        \
            const float* _p = h + (size_t)(n0 + ar) * IN_F + _k0 + aq * 8;       \
            float4 v0 = *(const float4*)_p;                                      \
            float4 v1 = *(const float4*)(_p + 4);                                \
            uint32_t hu[4], lu[4];                                               \
            split_pack(v0.x, v0.y, hu[0], lu[0]);                                \
            split_pack(v0.z, v0.w, hu[1], lu[1]);                                \
            split_pack(v1.x, v1.y, hu[2], lu[2]);                                \
            split_pack(v1.z, v1.w, hu[3], lu[3]);                                \
            const uint32_t _off = (uint32_t)(BUF) * 6144 + ar * 48 + aq * 16;    \
            *(uint4*)(sm + P_AHI + _off) = *(uint4*)hu;                          \
            *(uint4*)(sm + P_ALO + _off) = *(uint4*)lu;                          \
        }                                                                        \
        /* B: W^T tile [o][k], hi/lo split, u16 scatter */                       \
        {                                                                        \
            float4 wv = *(const float4*)(Wb + (size_t)(_k0 + bk) * OUT_F + bo4); \
            const float _w[4] = {wv.x, wv.y, wv.z, wv.w};                        \
            uint16_t* _bh = (uint16_t*)(sm + P_BHI + (BUF) * 3072);              \
            uint16_t* _bl = (uint16_t*)(sm + P_BLO + (BUF) * 3072);              \
            _Pragma("unroll")                                                    \
            for (int _j = 0; _j < 4; _j++) {                                     \
                __nv_bfloat16 _hi = __float2bfloat16(_w[_j]);                    \
                __nv_bfloat16 _lo = __float2bfloat16(_w[_j] - __bfloat162float(_hi)); \
                const int _i = (bo4 + _j) * 24 + bk;                             \
                _bh[_i] = __bfloat16_as_ushort(_hi);                             \
                _bl[_i] = __bfloat16_as_ushort(_lo);                             \
            }                                                                    \
        }                                                                        \
    } while (0)

    WH_STAGE(0, 0);
    __syncthreads();

    for (int c = 0; c < 32; c++) {
        const int buf = c & 1;
        if (c + 1 < 32) WH_STAGE(c + 1, 1 - buf);

        uint32_t ahi[4], alo[4];
        ldm4(ahi, smem_u + P_AHI + buf * 6144 + aLd);
        ldm4(alo, smem_u + P_ALO + buf * 6144 + aLd);
        #pragma unroll
        for (int g = 0; g < 4; g++) {
            uint32_t bh[4], bl[4];
            ldm4(bh, smem_u + P_BHI + buf * 3072 + bLd + g * 768);
            ldm4(bl, smem_u + P_BLO + buf * 3072 + bLd + g * 768);
            mma16816(acc[2 * g + 0], ahi, bh + 0);
            mma16816(acc[2 * g + 1], ahi, bh + 2);
            mma16816(acc[2 * g + 0], ahi, bl + 0);
            mma16816(acc[2 * g + 1], ahi, bl + 2);
            mma16816(acc[2 * g + 0], alo, bh + 0);
            mma16816(acc[2 * g + 1], alo, bh + 2);
        }
        __syncthreads();
    }

    // ---- T partials: shuffle-reduce over rows, stash per-warp ----
    {
        float* tr = (float*)(sm + P_TRED) + (t >> 5) * 64;
        #pragma unroll
        for (int f = 0; f < 8; f++) {
            float t0 = acc[f][0] + acc[f][2];
            float t1 = acc[f][1] + acc[f][3];
            #pragma unroll
            for (int off = 4; off < 32; off <<= 1) {
                t0 += __shfl_xor_sync(0xffffffffu, t0, off);
                t1 += __shfl_xor_sync(0xffffffffu, t1, off);
            }
            if (lane < 4) {
                tr[8 * f + 2 * lane]     = t0;
                tr[8 * f + 2 * lane + 1] = t1;
            }
        }
    }

    // ---- hi/lo split of Wh fragments into tiled u16 staging ----
    {
        uint16_t* shi = (uint16_t*)sm;
        uint16_t* slo = (uint16_t*)(sm + 16384);
        const int mrow = w16 + (lane >> 2);
        #pragma unroll
        for (int f = 0; f < 8; f++) {
            #pragma unroll
            for (int rr = 0; rr < 2; rr++) {
                const int m = mrow + rr * 8;
                #pragma unroll
                for (int cc = 0; cc < 2; cc++) {
                    const int o = 8 * f + 2 * (lane & 3) + cc;
                    float x = acc[f][rr * 2 + cc];
                    __nv_bfloat16 hi = __float2bfloat16(x);
                    __nv_bfloat16 lo = __float2bfloat16(x - __bfloat162float(hi));
                    const int idx = (m >> 3) * 512 + o * 8 + (m & 7);
                    shi[idx] = __bfloat16_as_ushort(hi);
                    slo[idx] = __bfloat16_as_ushort(lo);
                }
            }
        }
    }
    __syncthreads();

    // ---- T atomics ----
    if (t < 64) {
        const float* tr = (const float*)(sm + P_TRED);
        float s = 0.f;
        #pragma unroll
        for (int q = 0; q < 8; q++) s += tr[q * 64 + t];
        atomicAdd(&g_T[head * OUT_F + t], s);
    }

    // ---- copy staged tiles to global: tile = 8192 bf16 = 1024 uint4 each ----
    {
        uint4* dh = (uint4*)(g_Bhi + ((size_t)head * 512 + (n0 >> 3)) * 512);
        uint4* dl = (uint4*)(g_Blo + ((size_t)head * 512 + (n0 >> 3)) * 512);
        const uint4* sh4 = (const uint4*)sm;
        const uint4* sl4 = (const uint4*)(sm + 16384);
        #pragma unroll
        for (int q = 0; q < 4; q++) {
            dh[t + 256 * q] = sh4[t + 256 * q];
            dl[t + 256 * q] = sl4[t + 256 * q];
        }
    }
}

// ---------------------------------------------------------------------------
// Kernel B v3 (R8-proven): K-split masked aggregation, smem-staged B tiles.
// Grid (64, 8): x = n-tile | khalf<<5; y = head. atomicAdd partials into g_M.
// ---------------------------------------------------------------------------
#define ATTN_SMEM (1024 + 2 * 10240)

__global__ __launch_bounds__(128, 4) void attn_mma3_kernel()
{
    __shared__ __align__(16) char smem[ATTN_SMEM];
    const uint32_t smem_u = smem_to_u32(smem);
    const int tid  = threadIdx.x;
    const int wid  = tid >> 5;
    const int lane = tid & 31;
    const int n0   = (blockIdx.x & 31) * 128;
    const int kh   = blockIdx.x >> 5;
    const int head = blockIdx.y;

    const int so = tid & 63;
    const int sq = tid >> 6;
    const __nv_bfloat16* bhiH = g_Bhi + (size_t)head * 512 * 512;
    const __nv_bfloat16* bloH = g_Blo + (size_t)head * 512 * 512;
    const uint32_t stsA = (uint32_t)so * 80 + (uint32_t)sq * 16;
    const int kgbase = kh * 256;

    const int nb = n0 + wid * 32;
    const int r  = lane >> 2;
    const uint32_t* bp0 = g_adjbits + (size_t)(nb + r +  0) * 128 + kh * 64;
    const uint32_t* bp1 = g_adjbits + (size_t)(nb + r +  8) * 128 + kh * 64;
    const uint32_t* bp2 = g_adjbits + (size_t)(nb + r + 16) * 128 + kh * 64;
    const uint32_t* bp3 = g_adjbits + (size_t)(nb + r + 24) * 128 + kh * 64;

    const uint32_t bLd0 = (uint32_t)((lane & 7) + ((lane >> 4) & 1) * 8) * 80
                        + (uint32_t)((lane >> 3) & 1) * 16;

    float cM[2][8][4] = {};

    #define STAGE(CN, BUF) do {                                                  \
        const size_t _g0 = ((size_t)(kgbase + 4 * (CN) + sq) * 64 + so) * 8;     \
        const size_t _g1 = ((size_t)(kgbase + 4 * (CN) + sq + 2) * 64 + so) * 8; \
        uint4 _h0 = *(const uint4*)(bhiH + _g0);                                 \
        uint4 _h1 = *(const uint4*)(bhiH + _g1);                                 \
        uint4 _l0 = *(const uint4*)(bloH + _g0);                                 \
        uint4 _l1 = *(const uint4*)(bloH + _g1);                                 \
        char* _b = smem + 1024 + (BUF) * 10240;                                  \
        *(uint4*)(_b + stsA)              = _h0;                                 \
        *(uint4*)(_b + stsA + 32)         = _h1;                                 \
        *(uint4*)(_b + 5120 + stsA)       = _l0;                                 \
        *(uint4*)(_b + 5120 + stsA + 32)  = _l1;                                 \
    } while (0)

    STAGE(0, 0);
    __syncthreads();

    for (int c4 = 0; c4 < 16; c4++) {
        const uint4 bw0 = *(const uint4*)(bp0 + c4 * 4);
        const uint4 bw1 = *(const uint4*)(bp1 + c4 * 4);
        const uint4 bw2 = *(const uint4*)(bp2 + c4 * 4);
        const uint4 bw3 = *(const uint4*)(bp3 + c4 * 4);
        #pragma unroll
        for (int cc = 0; cc < 4; cc++) {
            const int c   = c4 * 4 + cc;
            const int cur = c & 1;
            if (c + 1 < 64) STAGE(c + 1, 1 - cur);

            const uint32_t w0 = cc == 0 ? bw0.x : cc == 1 ? bw0.y : cc == 2 ? bw0.z : bw0.w;
            const uint32_t w1 = cc == 0 ? bw1.x : cc == 1 ? bw1.y : cc == 2 ? bw1.z : bw1.w;
            const uint32_t w2 = cc == 0 ? bw2.x : cc == 1 ? bw2.y : cc == 2 ? bw2.z : bw2.w;
            const uint32_t w3 = cc == 0 ? bw3.x : cc == 1 ? bw3.y : cc == 2 ? bw3.z : bw3.w;

            const uint32_t bufB = smem_u + 1024 + (uint32_t)cur * 10240;
            #pragma unroll
            for (int ks = 0; ks < 2; ks++) {
                const int sh = ks * 16 + (lane & 3) * 2;
                uint32_t a0[4], a1[4];
                a0[0] = expand2(w0 >> sh);       a0[1] = expand2(w1 >> sh);
                a0[2] = expand2(w0 >> (sh + 8)); a0[3] = expand2(w1 >> (sh + 8));
                a1[0] = expand2(w2 >> sh);       a1[1] = expand2(w3 >> sh);
                a1[2] = expand2(w2 >> (sh + 8)); a1[3] = expand2(w3 >> (sh + 8));
                #pragma unroll
                for (int g = 0; g < 4; g++) {
                    uint32_t bh[4], bl[4];
                    const uint32_t bo = bLd0 + (uint32_t)g * 1280 + (uint32_t)ks * 32;
                    ldm4(bh, bufB + bo);
                    mma16816(cM[0][2 * g + 0], a0, bh + 0);
                    mma16816(cM[0][2 * g + 1], a0, bh + 2);
                    mma16816(cM[1][2 * g + 0], a1, bh + 0);
                    mma16816(cM[1][2 * g + 1], a1, bh + 2);
                    ldm4(bl, bufB + 5120 + bo);
                    mma16816(cM[0][2 * g + 0], a0, bl + 0);
                    mma16816(cM[0][2 * g + 1], a0, bl + 2);
                    mma16816(cM[1][2 * g + 0], a1, bl + 0);
                    mma16816(cM[1][2 * g + 1], a1, bl + 2);
                }
            }
            __syncthreads();
        }
    }

    // ---- epilogue: atomicAdd partial M ----
    const int col0 = (lane & 3) * 2;
    const int rowA = nb + (lane >> 2);
    #pragma unroll
    for (int tt = 0; tt < 2; tt++) {
        float* p0 = g_M + (size_t)(rowA + tt * 16) * (HEADS * OUT_F) + head * OUT_F;
        float* p1 = p0 + 8 * (HEADS * OUT_F);
        #pragma unroll
        for (int g2 = 0; g2 < 8; g2++) {
            const int o = g2 * 8 + col0;
            atomicAdd(p0 + o,     cM[tt][g2][0]);
            atomicAdd(p0 + o + 1, cM[tt][g2][1]);
            atomicAdd(p1 + o,     cM[tt][g2][2]);
            atomicAdd(p1 + o + 1, cM[tt][g2][3]);
        }
    }
}

// ---------------------------------------------------------------------------
// Fixup: out = elu( NEG_BIG * (T[col] - M) ), vectorized float4.
// ---------------------------------------------------------------------------
__global__ __launch_bounds__(256) void fixup_kernel(float* __restrict__ out)
{
    const int idx  = blockIdx.x * 256 + threadIdx.x;
    const int col  = (idx << 2) & 511;
    float4 m = *(const float4*)(g_M + (size_t)idx * 4);
    float4 tv = *(const float4*)(g_T + col);
    float x0 = NEG_BIG * (tv.x - m.x);
    float x1 = NEG_BIG * (tv.y - m.y);
    float x2 = NEG_BIG * (tv.z - m.z);
    float x3 = NEG_BIG * (tv.w - m.w);
    x0 = x0 > 0.f ? x0 : (expf(x0) - 1.0f);
    x1 = x1 > 0.f ? x1 : (expf(x1) - 1.0f);
    x2 = x2 > 0.f ? x2 : (expf(x2) - 1.0f);
    x3 = x3 > 0.f ? x3 : (expf(x3) - 1.0f);
    *(float4*)(out + (size_t)idx * 4) = make_float4(x0, x1, x2, x3);
}

// ---------------------------------------------------------------------------
extern "C" void kernel_launch(void* const* d_in, const int* in_sizes, int n_in,
                              void* d_out, int out_size)
{
    const float* h   = (const float*)d_in[0];   // [4096, 512] f32
    const int*   adj = (const int*)  d_in[1];   // [4096, 4096] i32
    const float* W   = (const float*)d_in[2];   // [8, 512, 64] f32
    float*       out = (float*)d_out;           // [4096, 512] f32

    (void)in_sizes; (void)n_in; (void)out_size;

    static float* tptr = nullptr;
    static float* mptr = nullptr;
    if (!tptr) cudaGetSymbolAddress((void**)&tptr, g_T);
    if (!mptr) cudaGetSymbolAddress((void**)&mptr, g_M);

    cudaMemsetAsync(tptr, 0, HEADS * OUT_F * sizeof(float), 0);
    cudaMemsetAsync(mptr, 0, (size_t)N_NODES * HEADS * OUT_F * sizeof(float), 0);

    adjbits_kernel<<<(N_NODES * (N_NODES / 32)) / 256, 256>>>(adj);

    prep_kernel<<<256, 256>>>(h, W);

    dim3 gB(64, HEADS);
    attn_mma3_kernel<<<gB, 128>>>();

    fixup_kernel<<<(N_NODES * HEADS * OUT_F / 4) / 256, 256>>>(out);
}